// round 14
// baseline (speedup 1.0000x reference)
#include <cuda_runtime.h>
#include <cuda_bf16.h>
#include <stdint.h>
#include <math.h>

#define B_ 64
#define K_ 8
#define T_ 12
#define H_ 2048
#define IN_ 2048
#define D_ 400
#define E_ 128
#define BK_ 512
#define G4H_ 8192
#define LDIH_ 4224
#define KM1_ 7
#define NHH_ ((size_t)BK_*H_)

__device__ float d_Zpre[T_*BK_*G4H_];
__device__ float d_Emb[T_*BK_*E_];
__device__ float d_ZxB[B_*G4H_];
__device__ float d_logpart[8*BK_*D_];
__device__ float d_Z[BK_*G4H_];
__device__ float d_c[BK_*H_];
__device__ float d_c2[BK_*H_];
__device__ float d_h2[BK_*H_];
__device__ float d_hd[BK_*H_];
__device__ float d_logits[BK_*D_];
__device__ float d_lpt[BK_*D_];
__device__ float d_gm[BK_*D_];
__device__ float d_G[2][BK_];
__device__ float d_logp[2][BK_];
__device__ float d_samp[2][BK_*T_];
__device__ float d_outs[2][BK_*T_];
__device__ float d_ent[B_];
__device__ float d_wpq[B_*KM1_];
__device__ float d_lgp[B_*KM1_];
__device__ int d_greedy[BK_];
__device__ int d_order[BK_];
__device__ int d_idxk[B_*K_];
__device__ float d_gval[B_*K_];
__device__ float d_entfull[BK_];

// bf16 hi/mid/lo planes (3 stacked copies each)
__device__ __nv_bfloat16 sWih[3ull*G4H_*LDIH_];
__device__ __nv_bfloat16 sWhh[3ull*G4H_*H_];
__device__ __nv_bfloat16 sWfc1[3ull*H_*H_];
__device__ __nv_bfloat16 sWout[3ull*D_*H_];
__device__ __nv_bfloat16 sX3[3ull*T_*BK_*IN_];
__device__ __nv_bfloat16 sEmb[3ull*T_*BK_*E_];
__device__ __nv_bfloat16 sXf[3ull*B_*IN_];
__device__ __nv_bfloat16 sH[3ull*BK_*H_];
__device__ __nv_bfloat16 sH2[3ull*BK_*H_];
__device__ __nv_bfloat16 sHd[3ull*BK_*H_];

__device__ __forceinline__ float sigf(float x) { return 1.f / (1.f + expf(-x)); }
__device__ __forceinline__ unsigned orderf(float f) {
    unsigned u = __float_as_uint(f);
    return (u & 0x80000000u) ? ~u : (u | 0x80000000u);
}
__device__ __forceinline__ float unorderf(unsigned e) {
    unsigned b = (e & 0x80000000u) ? (e ^ 0x80000000u) : ~e;
    return __uint_as_float(b);
}
__device__ __forceinline__ uint32_t smem_u32(const void* p) {
    uint32_t a;
    asm("{ .reg .u64 t; cvta.to.shared.u64 t, %1; cvt.u32.u64 %0, t; }" : "=r"(a) : "l"(p));
    return a;
}
__device__ __forceinline__ void ldm4(uint32_t* r, uint32_t addr) {
    asm volatile("ldmatrix.sync.aligned.m8n8.x4.shared.b16 {%0,%1,%2,%3}, [%4];"
        : "=r"(r[0]), "=r"(r[1]), "=r"(r[2]), "=r"(r[3]) : "r"(addr));
}
__device__ __forceinline__ void mma16816(float* c, const uint32_t* a, const uint32_t* b) {
    asm volatile("mma.sync.aligned.m16n8k16.row.col.f32.bf16.bf16.f32 "
        "{%0,%1,%2,%3}, {%4,%5,%6,%7}, {%8,%9}, {%0,%1,%2,%3};"
        : "+f"(c[0]), "+f"(c[1]), "+f"(c[2]), "+f"(c[3])
        : "r"(a[0]), "r"(a[1]), "r"(a[2]), "r"(a[3]), "r"(b[0]), "r"(b[1]));
}
__device__ __forceinline__ void cpa16(uint32_t dst, const void* src, int sz) {
    asm volatile("cp.async.ca.shared.global [%0], [%1], 16, %2;" :: "r"(dst), "l"(src), "r"(sz) : "memory");
}
__device__ __forceinline__ void wsplit(__nv_bfloat16* base, size_t plane, size_t i, float v) {
    __nv_bfloat16 h = __float2bfloat16(v);
    float vh = __bfloat162float(h);
    __nv_bfloat16 m = __float2bfloat16(v - vh);
    float vm = __bfloat162float(m);
    base[i] = h;
    base[plane + i] = m;
    base[2*plane + i] = __float2bfloat16(v - vh - vm);
}

// =====================================================================
// bf16x6 HMMA GEMM, tile BM x 256, BK=64, BM*4 threads (warp tile 32x64).
// cp.async double-buffered. kchunk != 0: split-K over gridDim.z.
// =====================================================================
template<int BM>
__global__ __launch_bounds__(BM*4, 1)
void gemm_hmma(const __nv_bfloat16* A, size_t Asz, int lda,
               const __nv_bfloat16* Bm, size_t Bsz, int ldb, int kbB,
               const float* Cin, const float* bias, const float* bias2, const float* zxb,
               float* C, int ldc, int M, int N, int K, int do_relu, int kchunk)
{
    extern __shared__ char smem[];
    constexpr int THREADS = BM * 4;
    constexpr int WR = BM / 32;              // warp rows
    constexpr int ABYTES = BM * 128;
    constexpr int CHB = ABYTES + 32768;

    if (kchunk) {
        int kz = blockIdx.z;
        A += (size_t)kz * kchunk;
        kbB += kz * kchunk;
        C += (size_t)kz * M * ldc;
        K = kchunk;
    }
    const int tid = threadIdx.x;
    const int wid = tid >> 5;
    const int lane = tid & 31;
    const int bm = blockIdx.y * BM;
    const int bn = blockIdx.x * 256;
    const int wm = (wid % WR) * 32;
    const int wn = (wid / WR) * 64;
    const uint32_t sbase = smem_u32(smem);

    float acc[2][8][4];
#pragma unroll
    for (int i = 0; i < 2; i++)
#pragma unroll
        for (int j = 0; j < 8; j++)
#pragma unroll
            for (int e = 0; e < 4; e++) acc[i][j][e] = 0.f;

    const int pa6[6] = {0, 0, 1, 1, 0, 2};
    const int pb6[6] = {0, 1, 0, 1, 2, 0};
    const int nkc = K >> 6;
    const int NC = 6 * nkc;

    auto stage_async = [&](int c, int buf) {
        int p = c / nkc;
        int kc = c - p * nkc;
        const __nv_bfloat16* Ap = A + (size_t)pa6[p] * Asz;
        const __nv_bfloat16* Bp = Bm + (size_t)pb6[p] * Bsz;
        int ka = kc * 64;
        int kb = kbB + kc * 64;
        uint32_t Ad = sbase + buf * CHB;
        uint32_t Bd = Ad + ABYTES;
#pragma unroll
        for (int i = 0; i < (BM*8)/THREADS; i++) {
            int idx = tid + i * THREADS;
            int r = idx >> 3;
            int cb = (idx & 7) << 4;
            int ok = (bm + r < M);
            const char* g = ok ? (const char*)(Ap + (size_t)(bm + r) * lda + ka) + cb
                               : (const char*)Ap;
            cpa16(Ad + r * 128 + (cb ^ ((r & 7) * 16)), g, ok ? 16 : 0);
        }
#pragma unroll
        for (int i = 0; i < 2048/THREADS; i++) {
            int idx = tid + i * THREADS;
            int r = idx >> 3;
            int cb = (idx & 7) << 4;
            int ok = (bn + r < N);
            const char* g = ok ? (const char*)(Bp + (size_t)(bn + r) * ldb + kb) + cb
                               : (const char*)Bp;
            cpa16(Bd + r * 128 + (cb ^ ((r & 7) * 16)), g, ok ? 16 : 0);
        }
        asm volatile("cp.async.commit_group;" ::: "memory");
    };

    auto compute = [&](int buf) {
        uint32_t Aad = sbase + buf * CHB;
        uint32_t Bad = Aad + ABYTES;
#pragma unroll
        for (int kk = 0; kk < 4; kk++) {
            uint32_t af[2][4];
            {
                int ro = ((lane >> 3) & 1) * 8 + (lane & 7);
                int co = kk * 32 + ((lane >> 4) & 1) * 16;
#pragma unroll
                for (int i = 0; i < 2; i++) {
                    int r = wm + i * 16 + ro;
                    ldm4(af[i], Aad + r * 128 + (co ^ ((r & 7) * 16)));
                }
            }
            uint32_t bfr[8][2];
            {
                int ro = ((lane >> 4) & 1) * 8 + (lane & 7);
                int co = kk * 32 + ((lane >> 3) & 1) * 16;
#pragma unroll
                for (int j2 = 0; j2 < 4; j2++) {
                    int r = wn + j2 * 16 + ro;
                    uint32_t t4[4];
                    ldm4(t4, Bad + r * 128 + (co ^ ((r & 7) * 16)));
                    bfr[j2*2][0] = t4[0]; bfr[j2*2][1] = t4[1];
                    bfr[j2*2+1][0] = t4[2]; bfr[j2*2+1][1] = t4[3];
                }
            }
#pragma unroll
            for (int i = 0; i < 2; i++)
#pragma unroll
                for (int j = 0; j < 8; j++)
                    mma16816(acc[i][j], af[i], bfr[j]);
        }
    };

    stage_async(0, 0);
    asm volatile("cp.async.wait_group 0;" ::: "memory");
    __syncthreads();
    for (int c = 0; c < NC; c++) {
        if (c + 1 < NC) stage_async(c + 1, (c + 1) & 1);
        compute(c & 1);
        if (c + 1 < NC) asm volatile("cp.async.wait_group 0;" ::: "memory");
        __syncthreads();
    }

#pragma unroll
    for (int i = 0; i < 2; i++) {
#pragma unroll
        for (int j = 0; j < 8; j++) {
            int r0 = bm + wm + i * 16 + (lane >> 2);
            int c0 = bn + wn + j * 8 + (lane & 3) * 2;
#pragma unroll
            for (int e = 0; e < 4; e++) {
                int m = r0 + (e >> 1) * 8;
                int n = c0 + (e & 1);
                if (m >= M || n >= N) continue;
                float v = acc[i][j][e];
                if (Cin) v += Cin[(size_t)m * ldc + n];
                if (bias) v += bias[n];
                if (bias2) v += bias2[n];
                if (zxb) v += zxb[(size_t)(m & 63) * ldc + n];
                if (do_relu) v = fmaxf(v, 0.f);
                C[(size_t)m * ldc + n] = v;
            }
        }
    }
}

// fp32 -> bf16 hi/mid/lo planes
__global__ void split3(const float* in, __nv_bfloat16* out, size_t n) {
    size_t i = (size_t)blockIdx.x * blockDim.x + threadIdx.x;
    if (i >= n) return;
    wsplit(out, n, i, in[i]);
}

// split-K reduce; optional bf16 plane output (plane size = total)
__global__ void reduce_k(const float* parts, int nparts, int total, int ncols,
                         const float* bias, float* out, int do_relu, __nv_bfloat16* bout) {
    int i = blockIdx.x * blockDim.x + threadIdx.x;
    if (i >= total) return;
    float s = 0.f;
    for (int p = 0; p < nparts; p++) s += parts[(size_t)p * total + i];
    if (bias) s += bias[i % ncols];
    if (do_relu) s = fmaxf(s, 0.f);
    out[i] = s;
    if (bout) wsplit(bout, (size_t)total, (size_t)i, s);
}

__global__ void zero_init() {
    int i = blockIdx.x * blockDim.x + threadIdx.x;
    int stride = gridDim.x * blockDim.x;
    for (int j = i; j < BK_*H_; j += stride) d_c[j] = 0.f;
    if (i < BK_) { d_G[0][i] = 0.f; d_logp[0][i] = 0.f; }
    if (i < BK_*T_) { d_samp[0][i] = 0.f; d_outs[0][i] = 0.f; }
    if (i < B_) d_ent[i] = 0.f;
}

__global__ void emb_kernel(const int* pop_all, const float* W_emb, const float* b_emb) {
    int i = blockIdx.x * blockDim.x + threadIdx.x;
    if (i >= T_*BK_*E_) return;
    int row = i >> 7;
    int e = i & 127;
    int p = pop_all[row];
    d_Emb[i] = fmaxf(W_emb[e*D_ + p] + b_emb[e], 0.f);
}

// LSTM pointwise; writes h2 fp32 + sH2 bf16 planes
__global__ void lstm_pw(const float* zsrc) {
    int i = blockIdx.x * blockDim.x + threadIdx.x;
    if (i >= BK_*H_) return;
    int bk = i >> 11;
    int col = i & 2047;
    const float* zr = zsrc + (size_t)bk * G4H_;
    float cn = sigf(zr[H_ + col]) * d_c[i] + sigf(zr[col]) * tanhf(zr[2*H_ + col]);
    d_c2[i] = cn;
    float hv = sigf(zr[3*H_ + col]) * tanhf(cn);
    d_h2[i] = hv;
    wsplit(sH2, NHH_, (size_t)i, hv);
}

__global__ void softmax_kernel(const int* pop_t, const float* mask, const float* u_t, int t, int src) {
    int bk = blockIdx.x;
    int tid = threadIdx.x;
    __shared__ float sm[D_];
    __shared__ float red[128];
    __shared__ unsigned long long redu[128];
    const float* lrow = d_logits + bk*D_;
    const float* mrow = mask + (size_t)pop_t[bk] * D_;
    float NEG_INF = __int_as_float(0xff800000);
    float lmax = NEG_INF;
    for (int d = tid; d < D_; d += 128) { float v = lrow[d] + mrow[d]; sm[d] = v; lmax = fmaxf(lmax, v); }
    red[tid] = lmax; __syncthreads();
    for (int s = 64; s > 0; s >>= 1) { if (tid < s) red[tid] = fmaxf(red[tid], red[tid+s]); __syncthreads(); }
    float M = red[0]; __syncthreads();
    float ssum = 0.f;
    for (int d = tid; d < D_; d += 128) ssum += expf(sm[d] - M);
    red[tid] = ssum; __syncthreads();
    for (int s = 64; s > 0; s >>= 1) { if (tid < s) red[tid] += red[tid+s]; __syncthreads(); }
    float logZ = M + logf(red[0]);
    unsigned long long bkey = 0ull;
    for (int d = tid; d < D_; d += 128) {
        unsigned long long key = ((unsigned long long)orderf(sm[d]) << 32) | (unsigned)(0xFFFFFFFFu - d);
        bkey = bkey > key ? bkey : key;
    }
    redu[tid] = bkey; __syncthreads();
    for (int s = 64; s > 0; s >>= 1) { if (tid < s) redu[tid] = redu[tid] > redu[tid+s] ? redu[tid] : redu[tid+s]; __syncthreads(); }
    if (tid == 0) d_greedy[bk] = (int)(0xFFFFFFFFu - (unsigned)(redu[0] & 0xFFFFFFFFu));
    for (int d = tid; d < D_; d += 128) d_lpt[bk*D_ + d] = sm[d] - logZ;
    if (t > 0) {
        float lpc = d_logp[src][bk];
        float Gc = d_G[src][bk];
        __syncthreads();
        for (int d = tid; d < D_; d += 128) {
            float uu = fminf(fmaxf(u_t[bk*D_ + d], 1e-9f), 1.f - 1e-9f);
            sm[d] = (sm[d] - logZ) + lpc + (-logf(-logf(uu)));
        }
        __syncthreads();
        float m2 = NEG_INF;
        for (int d = tid; d < D_; d += 128) m2 = fmaxf(m2, sm[d]);
        red[tid] = m2; __syncthreads();
        for (int s = 64; s > 0; s >>= 1) { if (tid < s) red[tid] = fmaxf(red[tid], red[tid+s]); __syncthreads(); }
        float Zm = red[0];
        for (int d = tid; d < D_; d += 128) {
            float gp = sm[d];
            float v = Gc - gp + log1pf(-expf(gp - Zm));
            d_gm[bk*D_ + d] = Gc - fmaxf(v, 0.f) - log1pf(expf(-fabsf(v)));
        }
    }
}

__global__ void topk_kernel() {
    int b = blockIdx.x;
    int tid = threadIdx.x;
    __shared__ unsigned long long red[128];
    __shared__ unsigned long long picked[K_];
    for (int it = 0; it < K_; it++) {
        unsigned long long best = 0ull;
        for (int cidx = tid; cidx < K_*D_; cidx += 128) {
            int k = cidx / D_;
            int d = cidx - k*D_;
            float v = d_gm[(k*B_ + b)*D_ + d];
            unsigned long long key = ((unsigned long long)orderf(v) << 32) | (unsigned)(0xFFFFFFFFu - cidx);
            bool skip = false;
            for (int j = 0; j < it; j++) { if (picked[j] == key) skip = true; }
            if (!skip) best = best > key ? best : key;
        }
        red[tid] = best; __syncthreads();
        for (int s = 64; s > 0; s >>= 1) { if (tid < s) red[tid] = red[tid] > red[tid+s] ? red[tid] : red[tid+s]; __syncthreads(); }
        if (tid == 0) {
            unsigned long long w = red[0];
            picked[it] = w;
            d_idxk[b*K_ + it] = (int)(0xFFFFFFFFu - (unsigned)(w & 0xFFFFFFFFu));
            d_gval[b*K_ + it] = unorderf((unsigned)(w >> 32));
        }
        __syncthreads();
    }
}

__global__ void beam_update(int t, int src) {
    int bk = threadIdx.x;
    int dst = src ^ 1;
    int k = bk >> 6;
    int b = bk & 63;
    int order;
    int sample;
    float Gn;
    if (t == 0) { order = bk; sample = d_greedy[bk]; Gn = d_G[src][bk]; }
    else {
        int cidx = d_idxk[b*K_ + k];
        int ks = cidx / D_;
        sample = cidx - ks*D_;
        order = ks*B_ + b;
        Gn = d_gval[b*K_ + k];
    }
    float sel = d_lpt[order*D_ + sample];
    d_G[dst][bk] = Gn;
    d_logp[dst][bk] = d_logp[src][order] + ((t == 0) ? 0.f : sel);
    d_order[bk] = order;
    for (int tt = 0; tt < T_; tt++) {
        d_samp[dst][bk*T_ + tt] = d_samp[src][order*T_ + tt];
        d_outs[dst][bk*T_ + tt] = d_outs[src][order*T_ + tt];
    }
    d_samp[dst][bk*T_ + t] = (float)sample;
    d_outs[dst][bk*T_ + t] = sel;
}

// gather h/c by beam order; writes c fp32 + sH bf16 planes
__global__ void gather_hc() {
    int i = blockIdx.x * blockDim.x + threadIdx.x;
    if (i >= BK_*H_) return;
    int bk = i >> 11;
    int col = i & 2047;
    int o = d_order[bk];
    float hv = d_h2[o*H_ + col];
    d_c[i] = d_c2[o*H_ + col];
    wsplit(sH, NHH_, (size_t)i, hv);
}

__global__ void entfull_kernel(const int* pop_t, const float* mask) {
    int warp = threadIdx.x >> 5;
    int lane = threadIdx.x & 31;
    int bk = blockIdx.x * 8 + warp;
    int o = d_order[bk];
    const float* lpr = d_lpt + o*D_;
    const float* mrow = mask + (size_t)pop_t[o] * D_;
    float s = 0.f;
    for (int d = lane; d < D_; d += 32) {
        float lp = lpr[d];
        if (mrow[d] == 0.f) s += lp * expf(lp);
    }
    for (int off = 16; off; off >>= 1) s += __shfl_down_sync(0xffffffffu, s, off);
    if (lane == 0) d_entfull[bk] = s;
}

__global__ void wq_kernel(int dst) {
    int b = threadIdx.x;
    if (b >= B_) return;
    float gk = d_gval[b*K_ + (K_-1)];
    float wsum = 0.f;
    float upd = 0.f;
    for (int k = 0; k < KM1_; k++) {
        float phi = d_logp[dst][k*B_ + b];
        float x = gk - phi;
        float gls;
        if (x >= 10.f) { float y = expf(-x); gls = -x - 0.5f*y + y*y*(1.f/24.f); }
        else gls = logf(-expm1f(-expf(-x)));
        float w = expf(phi - gls);
        d_wpq[b*KM1_ + k] = w;
        d_lgp[b*KM1_ + k] = phi;
        wsum += w;
        upd += w * d_entfull[k*B_ + b];
    }
    d_ent[b] += upd / wsum;
}

__global__ void epilogue(float* out) {
    int i = blockIdx.x * blockDim.x + threadIdx.x;
    if (i >= 11712) return;
    if (i < 5376) {
        int b = i / 84;
        int r = i % 84;
        out[i] = d_outs[0][((r / T_)*B_ + b)*T_ + (r % T_)];
    } else if (i < 10752) {
        int q = i - 5376;
        int b = q / 84;
        int r = q % 84;
        out[i] = d_samp[0][((r / T_)*B_ + b)*T_ + (r % T_)];
    } else if (i < 10816) out[i] = d_ent[i - 10752];
    else if (i < 11264) out[i] = d_wpq[i - 10816];
    else out[i] = d_lgp[i - 11264];
}

#define SMEM128 98304
#define SMEM64 81920
#define FNIL (const float*)0
#define BNIL (__nv_bfloat16*)0

extern "C" void kernel_launch(void* const* d_in, const int* in_sizes, int n_in,
                              void* d_out, int out_size)
{
    const float* x_f = (const float*)d_in[0];
    const float* x_f3 = (const float*)d_in[1];
    const float* gum_u = (const float*)d_in[2];
    const int* pop = (const int*)d_in[3];
    const float* mask = (const float*)d_in[4];
    const float* W_emb = (const float*)d_in[5];
    const float* b_emb = (const float*)d_in[6];
    const float* W_ih = (const float*)d_in[7];
    const float* W_hh = (const float*)d_in[8];
    const float* b_ih = (const float*)d_in[9];
    const float* b_hh = (const float*)d_in[10];
    const float* W_fc1 = (const float*)d_in[11];
    const float* b_fc1 = (const float*)d_in[12];
    const float* W_out = (const float*)d_in[13];
    const float* b_out = (const float*)d_in[14];

    float* pZpre;
    float* pEmb;
    float* pZxB;
    float* pZ;
    float* phd;
    float* plogits;
    float* plogp;
    cudaGetSymbolAddress((void**)&pZpre, d_Zpre);
    cudaGetSymbolAddress((void**)&pEmb, d_Emb);
    cudaGetSymbolAddress((void**)&pZxB, d_ZxB);
    cudaGetSymbolAddress((void**)&pZ, d_Z);
    cudaGetSymbolAddress((void**)&phd, d_hd);
    cudaGetSymbolAddress((void**)&plogits, d_logits);
    cudaGetSymbolAddress((void**)&plogp, d_logpart);
    __nv_bfloat16* pWih;
    __nv_bfloat16* pWhh;
    __nv_bfloat16* pWfc1;
    __nv_bfloat16* pWout;
    __nv_bfloat16* pX3;
    __nv_bfloat16* pSEmb;
    __nv_bfloat16* pXf;
    __nv_bfloat16* pH;
    __nv_bfloat16* pH2;
    __nv_bfloat16* pHd;
    cudaGetSymbolAddress((void**)&pWih, sWih);
    cudaGetSymbolAddress((void**)&pWhh, sWhh);
    cudaGetSymbolAddress((void**)&pWfc1, sWfc1);
    cudaGetSymbolAddress((void**)&pWout, sWout);
    cudaGetSymbolAddress((void**)&pX3, sX3);
    cudaGetSymbolAddress((void**)&pSEmb, sEmb);
    cudaGetSymbolAddress((void**)&pXf, sXf);
    cudaGetSymbolAddress((void**)&pH, sH);
    cudaGetSymbolAddress((void**)&pH2, sH2);
    cudaGetSymbolAddress((void**)&pHd, sHd);

    cudaFuncSetAttribute(gemm_hmma<128>, cudaFuncAttributeMaxDynamicSharedMemorySize, SMEM128);
    cudaFuncSetAttribute(gemm_hmma<64>, cudaFuncAttributeMaxDynamicSharedMemorySize, SMEM64);

    zero_init<<<2048, 512>>>();
    emb_kernel<<<(T_*BK_*E_ + 255)/256, 256>>>(pop, W_emb, b_emb);

    size_t nWih = (size_t)G4H_*LDIH_;
    size_t nWhh = (size_t)G4H_*H_;
    size_t nWfc1 = (size_t)H_*H_;
    size_t nWout = (size_t)D_*H_;
    size_t nX3 = (size_t)T_*BK_*IN_;
    size_t nEmb = (size_t)T_*BK_*E_;
    size_t nXf = (size_t)B_*IN_;
    split3<<<(unsigned)((nWih + 255)/256), 256>>>(W_ih, pWih, nWih);
    split3<<<(unsigned)((nWhh + 255)/256), 256>>>(W_hh, pWhh, nWhh);
    split3<<<(unsigned)((nWfc1 + 255)/256), 256>>>(W_fc1, pWfc1, nWfc1);
    split3<<<(unsigned)((nWout + 255)/256), 256>>>(W_out, pWout, nWout);
    split3<<<(unsigned)((nX3 + 255)/256), 256>>>(x_f3, pX3, nX3);
    split3<<<(unsigned)((nEmb + 255)/256), 256>>>(pEmb, pSEmb, nEmb);
    split3<<<(unsigned)((nXf + 255)/256), 256>>>(x_f, pXf, nXf);

    // ZxB = x_f @ W_ih[:, :IN].T  [64, 8192], split-K 4 (parts in d_Z)
    gemm_hmma<64><<<dim3(G4H_/256, 1, 4), 256, SMEM64>>>(
        pXf, nXf, IN_, pWih, nWih, LDIH_, 0,
        FNIL, FNIL, FNIL, FNIL,
        pZ, G4H_, B_, G4H_, IN_, 0, 512);
    reduce_k<<<(B_*G4H_ + 255)/256, 256>>>(pZ, 4, B_*G4H_, G4H_, FNIL, pZxB, 0, BNIL);

    // Zpre = Emb @ W_ih[:, IN:IN+E].T + b_ih + b_hh + ZxB[b]  [6144, 8192], K=128
    gemm_hmma<128><<<dim3(G4H_/256, T_*BK_/128), 512, SMEM128>>>(
        pSEmb, nEmb, E_, pWih, nWih, LDIH_, IN_,
        FNIL, b_ih, b_hh, pZxB,
        pZpre, G4H_, T_*BK_, G4H_, E_, 0, 0);

    // Zpre += x_f3 @ W_ih[:, IN+E:].T  [6144, 8192], K=2048
    gemm_hmma<128><<<dim3(G4H_/256, T_*BK_/128), 512, SMEM128>>>(
        pX3, nX3, IN_, pWih, nWih, LDIH_, IN_ + E_,
        pZpre, FNIL, FNIL, FNIL,
        pZpre, G4H_, T_*BK_, G4H_, IN_, 0, 0);

    for (int t = 0; t < T_; t++) {
        int src = t & 1;
        const float* zsrc = pZpre + (size_t)t*BK_*G4H_;
        if (t > 0) {
            gemm_hmma<128><<<dim3(G4H_/256, BK_/128), 512, SMEM128>>>(
                pH, NHH_, H_, pWhh, nWhh, H_, 0,
                zsrc, FNIL, FNIL, FNIL,
                pZ, G4H_, BK_, G4H_, H_, 0, 0);
            zsrc = pZ;
        }
        lstm_pw<<<(BK_*H_ + 255)/256, 256>>>(zsrc);
        // fc1: split-K 2, parts in d_Z, reduce applies bias+relu and emits sHd planes
        gemm_hmma<64><<<dim3(H_/256, BK_/64, 2), 256, SMEM64>>>(
            pH2, NHH_, H_, pWfc1, nWfc1, H_, 0,
            FNIL, FNIL, FNIL, FNIL,
            pZ, H_, BK_, H_, H_, 0, 1024);
        reduce_k<<<(BK_*H_ + 255)/256, 256>>>(pZ, 2, BK_*H_, H_, b_fc1, phd, 1, pHd);
        // logits: split-K 8
        gemm_hmma<64><<<dim3(2, BK_/64, 8), 256, SMEM64>>>(
            pHd, NHH_, H_, pWout, nWout, H_, 0,
            FNIL, FNIL, FNIL, FNIL,
            plogp, D_, BK_, D_, H_, 0, 256);
        reduce_k<<<(BK_*D_ + 255)/256, 256>>>(plogp, 8, BK_*D_, D_, b_out, plogits, 0, BNIL);

        softmax_kernel<<<BK_, 128>>>(pop + t*BK_, mask, gum_u + (size_t)t*BK_*D_, t, src);
        if (t > 0) topk_kernel<<<B_, 128>>>();
        beam_update<<<1, BK_>>>(t, src);
        gather_hc<<<(BK_*H_ + 255)/256, 256>>>();
        if (t > 0) {
            entfull_kernel<<<B_, 256>>>(pop + t*BK_, mask);
            wq_kernel<<<1, B_>>>(src ^ 1);
        }
    }
    epilogue<<<(11712 + 255)/256, 256>>>((float*)d_out);
}

// round 15
// speedup vs baseline: 1.6923x; 1.6923x over previous
#include <cuda_runtime.h>
#include <cuda_fp16.h>
#include <cuda_bf16.h>
#include <stdint.h>
#include <math.h>

#define B_ 64
#define K_ 8
#define T_ 12
#define H_ 2048
#define IN_ 2048
#define D_ 400
#define E_ 128
#define BK_ 512
#define G4H_ 8192
#define LDIH_ 4224
#define KM1_ 7
#define NHH_ ((size_t)BK_*H_)

__device__ float d_Zpre[T_*BK_*G4H_];
__device__ float d_Emb[T_*BK_*E_];
__device__ float d_ZxB[B_*G4H_];
__device__ float d_logpart[8*BK_*D_];
__device__ float d_Z[BK_*G4H_];
__device__ float d_c[BK_*H_];
__device__ float d_c2[BK_*H_];
__device__ float d_h2[BK_*H_];
__device__ float d_hd[BK_*H_];
__device__ float d_logits[BK_*D_];
__device__ float d_lpt[BK_*D_];
__device__ float d_gm[BK_*D_];
__device__ float d_G[2][BK_];
__device__ float d_logp[2][BK_];
__device__ float d_samp[2][BK_*T_];
__device__ float d_outs[2][BK_*T_];
__device__ float d_ent[B_];
__device__ float d_wpq[B_*KM1_];
__device__ float d_lgp[B_*KM1_];
__device__ int d_greedy[BK_];
__device__ int d_order[BK_];
__device__ int d_idxk[B_*K_];
__device__ float d_gval[B_*K_];
__device__ float d_entfull[BK_];

// fp16 h/m' planes (2 stacked copies each; m' = (v-h)*2048)
__device__ __half sWih[2ull*G4H_*LDIH_];
__device__ __half sWhh[2ull*G4H_*H_];
__device__ __half sWfc1[2ull*H_*H_];
__device__ __half sWout[2ull*D_*H_];
__device__ __half sX3[2ull*T_*BK_*IN_];
__device__ __half sEmb[2ull*T_*BK_*E_];
__device__ __half sXf[2ull*B_*IN_];
__device__ __half sH[2ull*BK_*H_];
__device__ __half sH2[2ull*BK_*H_];
__device__ __half sHd[2ull*BK_*H_];

__device__ __forceinline__ float sigf(float x) { return 1.f / (1.f + expf(-x)); }
__device__ __forceinline__ unsigned orderf(float f) {
    unsigned u = __float_as_uint(f);
    return (u & 0x80000000u) ? ~u : (u | 0x80000000u);
}
__device__ __forceinline__ float unorderf(unsigned e) {
    unsigned b = (e & 0x80000000u) ? (e ^ 0x80000000u) : ~e;
    return __uint_as_float(b);
}
__device__ __forceinline__ uint32_t smem_u32(const void* p) {
    uint32_t a;
    asm("{ .reg .u64 t; cvta.to.shared.u64 t, %1; cvt.u32.u64 %0, t; }" : "=r"(a) : "l"(p));
    return a;
}
__device__ __forceinline__ void ldm4(uint32_t* r, uint32_t addr) {
    asm volatile("ldmatrix.sync.aligned.m8n8.x4.shared.b16 {%0,%1,%2,%3}, [%4];"
        : "=r"(r[0]), "=r"(r[1]), "=r"(r[2]), "=r"(r[3]) : "r"(addr));
}
__device__ __forceinline__ void mma16816(float* c, const uint32_t* a, const uint32_t* b) {
    asm volatile("mma.sync.aligned.m16n8k16.row.col.f32.f16.f16.f32 "
        "{%0,%1,%2,%3}, {%4,%5,%6,%7}, {%8,%9}, {%0,%1,%2,%3};"
        : "+f"(c[0]), "+f"(c[1]), "+f"(c[2]), "+f"(c[3])
        : "r"(a[0]), "r"(a[1]), "r"(a[2]), "r"(a[3]), "r"(b[0]), "r"(b[1]));
}
__device__ __forceinline__ void cpa16(uint32_t dst, const void* src, int sz) {
    asm volatile("cp.async.ca.shared.global [%0], [%1], 16, %2;" :: "r"(dst), "l"(src), "r"(sz) : "memory");
}
__device__ __forceinline__ void wsplit2(__half* base, size_t plane, size_t i, float v) {
    __half h = __float2half(v);
    float vh = __half2float(h);
    base[i] = h;
    base[plane + i] = __float2half((v - vh) * 2048.0f);
}

// =====================================================================
// fp16 Horner-split HMMA GEMM: C = act(descale applied internally)
// acc = (A_h B_m' + A_m' B_h); acc *= 1/2048; acc += A_h B_h.
// Tile BM x 256, BK=64, 256 threads (8 warps, warp tile (BM/2) x 64).
// cp.async double-buffered. kchunk != 0: split-K over gridDim.z.
// =====================================================================
template<int BM>
__global__ __launch_bounds__(256)
void gemm_hmma(const __half* A, size_t Asz, int lda,
               const __half* Bm, size_t Bsz, int ldb, int kbB,
               const float* Cin, const float* bias, const float* bias2, const float* zxb,
               float* C, int ldc, int M, int N, int K, int do_relu, int kchunk)
{
    extern __shared__ char smem[];
    constexpr int MI = BM / 32;
    constexpr int ABYTES = BM * 128;
    constexpr int CHB = ABYTES + 32768;

    if (kchunk) {
        int kz = blockIdx.z;
        A += (size_t)kz * kchunk;
        kbB += kz * kchunk;
        C += (size_t)kz * M * ldc;
        K = kchunk;
    }
    const int tid = threadIdx.x;
    const int wid = tid >> 5;
    const int lane = tid & 31;
    const int bm = blockIdx.y * BM;
    const int bn = blockIdx.x * 256;
    const int wm = (wid & 1) * (BM / 2);
    const int wn = (wid >> 1) * 64;
    const uint32_t sbase = smem_u32(smem);

    float acc[MI][8][4];
#pragma unroll
    for (int i = 0; i < MI; i++)
#pragma unroll
        for (int j = 0; j < 8; j++)
#pragma unroll
            for (int e = 0; e < 4; e++) acc[i][j][e] = 0.f;

    // pass 0: A_h * B_m'; pass 1: A_m' * B_h; rescale; pass 2: A_h * B_h
    const int pa3[3] = {0, 1, 0};
    const int pb3[3] = {1, 0, 0};
    const int nkc = K >> 6;
    const int NC = 3 * nkc;

    auto stage_async = [&](int c, int buf) {
        int p = c / nkc;
        int kc = c - p * nkc;
        const __half* Ap = A + (size_t)pa3[p] * Asz;
        const __half* Bp = Bm + (size_t)pb3[p] * Bsz;
        int ka = kc * 64;
        int kb = kbB + kc * 64;
        uint32_t Ad = sbase + buf * CHB;
        uint32_t Bd = Ad + ABYTES;
#pragma unroll
        for (int i = 0; i < BM/32; i++) {
            int idx = tid + i * 256;
            int r = idx >> 3;
            int cb = (idx & 7) << 4;
            int ok = (bm + r < M);
            const char* g = ok ? (const char*)(Ap + (size_t)(bm + r) * lda + ka) + cb
                               : (const char*)Ap;
            cpa16(Ad + r * 128 + (cb ^ ((r & 7) * 16)), g, ok ? 16 : 0);
        }
#pragma unroll
        for (int i = 0; i < 8; i++) {
            int idx = tid + i * 256;
            int r = idx >> 3;
            int cb = (idx & 7) << 4;
            int ok = (bn + r < N);
            const char* g = ok ? (const char*)(Bp + (size_t)(bn + r) * ldb + kb) + cb
                               : (const char*)Bp;
            cpa16(Bd + r * 128 + (cb ^ ((r & 7) * 16)), g, ok ? 16 : 0);
        }
        asm volatile("cp.async.commit_group;" ::: "memory");
    };

    auto compute = [&](int buf) {
        uint32_t Aad = sbase + buf * CHB;
        uint32_t Bad = Aad + ABYTES;
#pragma unroll
        for (int kk = 0; kk < 4; kk++) {
            uint32_t af[MI][4];
            {
                int ro = ((lane >> 3) & 1) * 8 + (lane & 7);
                int co = kk * 32 + ((lane >> 4) & 1) * 16;
#pragma unroll
                for (int i = 0; i < MI; i++) {
                    int r = wm + i * 16 + ro;
                    ldm4(af[i], Aad + r * 128 + (co ^ ((r & 7) * 16)));
                }
            }
            uint32_t bfr[8][2];
            {
                int ro = ((lane >> 4) & 1) * 8 + (lane & 7);
                int co = kk * 32 + ((lane >> 3) & 1) * 16;
#pragma unroll
                for (int j2 = 0; j2 < 4; j2++) {
                    int r = wn + j2 * 16 + ro;
                    uint32_t t4[4];
                    ldm4(t4, Bad + r * 128 + (co ^ ((r & 7) * 16)));
                    bfr[j2*2][0] = t4[0]; bfr[j2*2][1] = t4[1];
                    bfr[j2*2+1][0] = t4[2]; bfr[j2*2+1][1] = t4[3];
                }
            }
#pragma unroll
            for (int i = 0; i < MI; i++)
#pragma unroll
                for (int j = 0; j < 8; j++)
                    mma16816(acc[i][j], af[i], bfr[j]);
        }
    };

    stage_async(0, 0);
    asm volatile("cp.async.wait_group 0;" ::: "memory");
    __syncthreads();
    for (int c = 0; c < NC; c++) {
        if (c == 2 * nkc) {
            const float s = 1.0f / 2048.0f;
#pragma unroll
            for (int i = 0; i < MI; i++)
#pragma unroll
                for (int j = 0; j < 8; j++)
#pragma unroll
                    for (int e = 0; e < 4; e++) acc[i][j][e] *= s;
        }
        if (c + 1 < NC) stage_async(c + 1, (c + 1) & 1);
        compute(c & 1);
        if (c + 1 < NC) asm volatile("cp.async.wait_group 0;" ::: "memory");
        __syncthreads();
    }

#pragma unroll
    for (int i = 0; i < MI; i++) {
#pragma unroll
        for (int j = 0; j < 8; j++) {
            int r0 = bm + wm + i * 16 + (lane >> 2);
            int c0 = bn + wn + j * 8 + (lane & 3) * 2;
#pragma unroll
            for (int e = 0; e < 4; e++) {
                int m = r0 + (e >> 1) * 8;
                int n = c0 + (e & 1);
                if (m >= M || n >= N) continue;
                float v = acc[i][j][e];
                if (Cin) v += Cin[(size_t)m * ldc + n];
                if (bias) v += bias[n];
                if (bias2) v += bias2[n];
                if (zxb) v += zxb[(size_t)(m & 63) * ldc + n];
                if (do_relu) v = fmaxf(v, 0.f);
                C[(size_t)m * ldc + n] = v;
            }
        }
    }
}

// fp32 -> fp16 h/m' planes
__global__ void split2(const float* in, __half* out, size_t n) {
    size_t i = (size_t)blockIdx.x * blockDim.x + threadIdx.x;
    if (i >= n) return;
    wsplit2(out, n, i, in[i]);
}

// split-K reduce; optional fp16 plane output (plane size = total)
__global__ void reduce_k(const float* parts, int nparts, int total, int ncols,
                         const float* bias, float* out, int do_relu, __half* bout) {
    int i = blockIdx.x * blockDim.x + threadIdx.x;
    if (i >= total) return;
    float s = 0.f;
    for (int p = 0; p < nparts; p++) s += parts[(size_t)p * total + i];
    if (bias) s += bias[i % ncols];
    if (do_relu) s = fmaxf(s, 0.f);
    out[i] = s;
    if (bout) wsplit2(bout, (size_t)total, (size_t)i, s);
}

__global__ void zero_init() {
    int i = blockIdx.x * blockDim.x + threadIdx.x;
    int stride = gridDim.x * blockDim.x;
    for (int j = i; j < BK_*H_; j += stride) d_c[j] = 0.f;
    if (i < BK_) { d_G[0][i] = 0.f; d_logp[0][i] = 0.f; }
    if (i < BK_*T_) { d_samp[0][i] = 0.f; d_outs[0][i] = 0.f; }
    if (i < B_) d_ent[i] = 0.f;
}

__global__ void emb_kernel(const int* pop_all, const float* W_emb, const float* b_emb) {
    int i = blockIdx.x * blockDim.x + threadIdx.x;
    if (i >= T_*BK_*E_) return;
    int row = i >> 7;
    int e = i & 127;
    int p = pop_all[row];
    d_Emb[i] = fmaxf(W_emb[e*D_ + p] + b_emb[e], 0.f);
}

// LSTM pointwise; writes h2 fp32 + sH2 planes
__global__ void lstm_pw(const float* zsrc) {
    int i = blockIdx.x * blockDim.x + threadIdx.x;
    if (i >= BK_*H_) return;
    int bk = i >> 11;
    int col = i & 2047;
    const float* zr = zsrc + (size_t)bk * G4H_;
    float cn = sigf(zr[H_ + col]) * d_c[i] + sigf(zr[col]) * tanhf(zr[2*H_ + col]);
    d_c2[i] = cn;
    float hv = sigf(zr[3*H_ + col]) * tanhf(cn);
    d_h2[i] = hv;
    wsplit2(sH2, NHH_, (size_t)i, hv);
}

__global__ void softmax_kernel(const int* pop_t, const float* mask, const float* u_t, int t, int src) {
    int bk = blockIdx.x;
    int tid = threadIdx.x;
    __shared__ float sm[D_];
    __shared__ float red[128];
    __shared__ unsigned long long redu[128];
    const float* lrow = d_logits + bk*D_;
    const float* mrow = mask + (size_t)pop_t[bk] * D_;
    float NEG_INF = __int_as_float(0xff800000);
    float lmax = NEG_INF;
    for (int d = tid; d < D_; d += 128) { float v = lrow[d] + mrow[d]; sm[d] = v; lmax = fmaxf(lmax, v); }
    red[tid] = lmax; __syncthreads();
    for (int s = 64; s > 0; s >>= 1) { if (tid < s) red[tid] = fmaxf(red[tid], red[tid+s]); __syncthreads(); }
    float M = red[0]; __syncthreads();
    float ssum = 0.f;
    for (int d = tid; d < D_; d += 128) ssum += expf(sm[d] - M);
    red[tid] = ssum; __syncthreads();
    for (int s = 64; s > 0; s >>= 1) { if (tid < s) red[tid] += red[tid+s]; __syncthreads(); }
    float logZ = M + logf(red[0]);
    unsigned long long bkey = 0ull;
    for (int d = tid; d < D_; d += 128) {
        unsigned long long key = ((unsigned long long)orderf(sm[d]) << 32) | (unsigned)(0xFFFFFFFFu - d);
        bkey = bkey > key ? bkey : key;
    }
    redu[tid] = bkey; __syncthreads();
    for (int s = 64; s > 0; s >>= 1) { if (tid < s) redu[tid] = redu[tid] > redu[tid+s] ? redu[tid] : redu[tid+s]; __syncthreads(); }
    if (tid == 0) d_greedy[bk] = (int)(0xFFFFFFFFu - (unsigned)(redu[0] & 0xFFFFFFFFu));
    for (int d = tid; d < D_; d += 128) d_lpt[bk*D_ + d] = sm[d] - logZ;
    if (t > 0) {
        float lpc = d_logp[src][bk];
        float Gc = d_G[src][bk];
        __syncthreads();
        for (int d = tid; d < D_; d += 128) {
            float uu = fminf(fmaxf(u_t[bk*D_ + d], 1e-9f), 1.f - 1e-9f);
            sm[d] = (sm[d] - logZ) + lpc + (-logf(-logf(uu)));
        }
        __syncthreads();
        float m2 = NEG_INF;
        for (int d = tid; d < D_; d += 128) m2 = fmaxf(m2, sm[d]);
        red[tid] = m2; __syncthreads();
        for (int s = 64; s > 0; s >>= 1) { if (tid < s) red[tid] = fmaxf(red[tid], red[tid+s]); __syncthreads(); }
        float Zm = red[0];
        for (int d = tid; d < D_; d += 128) {
            float gp = sm[d];
            float v = Gc - gp + log1pf(-expf(gp - Zm));
            d_gm[bk*D_ + d] = Gc - fmaxf(v, 0.f) - log1pf(expf(-fabsf(v)));
        }
    }
}

__global__ void topk_kernel() {
    int b = blockIdx.x;
    int tid = threadIdx.x;
    __shared__ unsigned long long red[128];
    __shared__ unsigned long long picked[K_];
    for (int it = 0; it < K_; it++) {
        unsigned long long best = 0ull;
        for (int cidx = tid; cidx < K_*D_; cidx += 128) {
            int k = cidx / D_;
            int d = cidx - k*D_;
            float v = d_gm[(k*B_ + b)*D_ + d];
            unsigned long long key = ((unsigned long long)orderf(v) << 32) | (unsigned)(0xFFFFFFFFu - cidx);
            bool skip = false;
            for (int j = 0; j < it; j++) { if (picked[j] == key) skip = true; }
            if (!skip) best = best > key ? best : key;
        }
        red[tid] = best; __syncthreads();
        for (int s = 64; s > 0; s >>= 1) { if (tid < s) red[tid] = red[tid] > red[tid+s] ? red[tid] : red[tid+s]; __syncthreads(); }
        if (tid == 0) {
            unsigned long long w = red[0];
            picked[it] = w;
            d_idxk[b*K_ + it] = (int)(0xFFFFFFFFu - (unsigned)(w & 0xFFFFFFFFu));
            d_gval[b*K_ + it] = unorderf((unsigned)(w >> 32));
        }
        __syncthreads();
    }
}

__global__ void beam_update(int t, int src) {
    int bk = threadIdx.x;
    int dst = src ^ 1;
    int k = bk >> 6;
    int b = bk & 63;
    int order;
    int sample;
    float Gn;
    if (t == 0) { order = bk; sample = d_greedy[bk]; Gn = d_G[src][bk]; }
    else {
        int cidx = d_idxk[b*K_ + k];
        int ks = cidx / D_;
        sample = cidx - ks*D_;
        order = ks*B_ + b;
        Gn = d_gval[b*K_ + k];
    }
    float sel = d_lpt[order*D_ + sample];
    d_G[dst][bk] = Gn;
    d_logp[dst][bk] = d_logp[src][order] + ((t == 0) ? 0.f : sel);
    d_order[bk] = order;
    for (int tt = 0; tt < T_; tt++) {
        d_samp[dst][bk*T_ + tt] = d_samp[src][order*T_ + tt];
        d_outs[dst][bk*T_ + tt] = d_outs[src][order*T_ + tt];
    }
    d_samp[dst][bk*T_ + t] = (float)sample;
    d_outs[dst][bk*T_ + t] = sel;
}

// gather h/c by beam order; writes c fp32 + sH planes
__global__ void gather_hc() {
    int i = blockIdx.x * blockDim.x + threadIdx.x;
    if (i >= BK_*H_) return;
    int bk = i >> 11;
    int col = i & 2047;
    int o = d_order[bk];
    float hv = d_h2[o*H_ + col];
    d_c[i] = d_c2[o*H_ + col];
    wsplit2(sH, NHH_, (size_t)i, hv);
}

__global__ void entfull_kernel(const int* pop_t, const float* mask) {
    int warp = threadIdx.x >> 5;
    int lane = threadIdx.x & 31;
    int bk = blockIdx.x * 8 + warp;
    int o = d_order[bk];
    const float* lpr = d_lpt + o*D_;
    const float* mrow = mask + (size_t)pop_t[o] * D_;
    float s = 0.f;
    for (int d = lane; d < D_; d += 32) {
        float lp = lpr[d];
        if (mrow[d] == 0.f) s += lp * expf(lp);
    }
    for (int off = 16; off; off >>= 1) s += __shfl_down_sync(0xffffffffu, s, off);
    if (lane == 0) d_entfull[bk] = s;
}

__global__ void wq_kernel(int dst) {
    int b = threadIdx.x;
    if (b >= B_) return;
    float gk = d_gval[b*K_ + (K_-1)];
    float wsum = 0.f;
    float upd = 0.f;
    for (int k = 0; k < KM1_; k++) {
        float phi = d_logp[dst][k*B_ + b];
        float x = gk - phi;
        float gls;
        if (x >= 10.f) { float y = expf(-x); gls = -x - 0.5f*y + y*y*(1.f/24.f); }
        else gls = logf(-expm1f(-expf(-x)));
        float w = expf(phi - gls);
        d_wpq[b*KM1_ + k] = w;
        d_lgp[b*KM1_ + k] = phi;
        wsum += w;
        upd += w * d_entfull[k*B_ + b];
    }
    d_ent[b] += upd / wsum;
}

__global__ void epilogue(float* out) {
    int i = blockIdx.x * blockDim.x + threadIdx.x;
    if (i >= 11712) return;
    if (i < 5376) {
        int b = i / 84;
        int r = i % 84;
        out[i] = d_outs[0][((r / T_)*B_ + b)*T_ + (r % T_)];
    } else if (i < 10752) {
        int q = i - 5376;
        int b = q / 84;
        int r = q % 84;
        out[i] = d_samp[0][((r / T_)*B_ + b)*T_ + (r % T_)];
    } else if (i < 10816) out[i] = d_ent[i - 10752];
    else if (i < 11264) out[i] = d_wpq[i - 10816];
    else out[i] = d_lgp[i - 11264];
}

#define SMEM128 98304
#define SMEM64 81920
#define FNIL (const float*)0
#define HNIL (__half*)0

extern "C" void kernel_launch(void* const* d_in, const int* in_sizes, int n_in,
                              void* d_out, int out_size)
{
    const float* x_f = (const float*)d_in[0];
    const float* x_f3 = (const float*)d_in[1];
    const float* gum_u = (const float*)d_in[2];
    const int* pop = (const int*)d_in[3];
    const float* mask = (const float*)d_in[4];
    const float* W_emb = (const float*)d_in[5];
    const float* b_emb = (const float*)d_in[6];
    const float* W_ih = (const float*)d_in[7];
    const float* W_hh = (const float*)d_in[8];
    const float* b_ih = (const float*)d_in[9];
    const float* b_hh = (const float*)d_in[10];
    const float* W_fc1 = (const float*)d_in[11];
    const float* b_fc1 = (const float*)d_in[12];
    const float* W_out = (const float*)d_in[13];
    const float* b_out = (const float*)d_in[14];

    float* pZpre;
    float* pEmb;
    float* pZxB;
    float* pZ;
    float* phd;
    float* plogits;
    float* plogp;
    cudaGetSymbolAddress((void**)&pZpre, d_Zpre);
    cudaGetSymbolAddress((void**)&pEmb, d_Emb);
    cudaGetSymbolAddress((void**)&pZxB, d_ZxB);
    cudaGetSymbolAddress((void**)&pZ, d_Z);
    cudaGetSymbolAddress((void**)&phd, d_hd);
    cudaGetSymbolAddress((void**)&plogits, d_logits);
    cudaGetSymbolAddress((void**)&plogp, d_logpart);
    __half* pWih;
    __half* pWhh;
    __half* pWfc1;
    __half* pWout;
    __half* pX3;
    __half* pSEmb;
    __half* pXf;
    __half* pH;
    __half* pH2;
    __half* pHd;
    cudaGetSymbolAddress((void**)&pWih, sWih);
    cudaGetSymbolAddress((void**)&pWhh, sWhh);
    cudaGetSymbolAddress((void**)&pWfc1, sWfc1);
    cudaGetSymbolAddress((void**)&pWout, sWout);
    cudaGetSymbolAddress((void**)&pX3, sX3);
    cudaGetSymbolAddress((void**)&pSEmb, sEmb);
    cudaGetSymbolAddress((void**)&pXf, sXf);
    cudaGetSymbolAddress((void**)&pH, sH);
    cudaGetSymbolAddress((void**)&pH2, sH2);
    cudaGetSymbolAddress((void**)&pHd, sHd);

    cudaFuncSetAttribute(gemm_hmma<128>, cudaFuncAttributeMaxDynamicSharedMemorySize, SMEM128);
    cudaFuncSetAttribute(gemm_hmma<64>, cudaFuncAttributeMaxDynamicSharedMemorySize, SMEM64);

    zero_init<<<2048, 512>>>();
    emb_kernel<<<(T_*BK_*E_ + 255)/256, 256>>>(pop, W_emb, b_emb);

    size_t nWih = (size_t)G4H_*LDIH_;
    size_t nWhh = (size_t)G4H_*H_;
    size_t nWfc1 = (size_t)H_*H_;
    size_t nWout = (size_t)D_*H_;
    size_t nX3 = (size_t)T_*BK_*IN_;
    size_t nEmb = (size_t)T_*BK_*E_;
    size_t nXf = (size_t)B_*IN_;
    split2<<<(unsigned)((nWih + 255)/256), 256>>>(W_ih, pWih, nWih);
    split2<<<(unsigned)((nWhh + 255)/256), 256>>>(W_hh, pWhh, nWhh);
    split2<<<(unsigned)((nWfc1 + 255)/256), 256>>>(W_fc1, pWfc1, nWfc1);
    split2<<<(unsigned)((nWout + 255)/256), 256>>>(W_out, pWout, nWout);
    split2<<<(unsigned)((nX3 + 255)/256), 256>>>(x_f3, pX3, nX3);
    split2<<<(unsigned)((nEmb + 255)/256), 256>>>(pEmb, pSEmb, nEmb);
    split2<<<(unsigned)((nXf + 255)/256), 256>>>(x_f, pXf, nXf);

    // ZxB = x_f @ W_ih[:, :IN].T  [64, 8192], split-K 4 (parts in d_Z)
    gemm_hmma<64><<<dim3(G4H_/256, 1, 4), 256, SMEM64>>>(
        pXf, nXf, IN_, pWih, nWih, LDIH_, 0,
        FNIL, FNIL, FNIL, FNIL,
        pZ, G4H_, B_, G4H_, IN_, 0, 512);
    reduce_k<<<(B_*G4H_ + 255)/256, 256>>>(pZ, 4, B_*G4H_, G4H_, FNIL, pZxB, 0, HNIL);

    // Zpre = Emb @ W_ih[:, IN:IN+E].T + b_ih + b_hh + ZxB[b]  [6144, 8192], K=128
    gemm_hmma<128><<<dim3(G4H_/256, T_*BK_/128), 256, SMEM128>>>(
        pSEmb, nEmb, E_, pWih, nWih, LDIH_, IN_,
        FNIL, b_ih, b_hh, pZxB,
        pZpre, G4H_, T_*BK_, G4H_, E_, 0, 0);

    // Zpre += x_f3 @ W_ih[:, IN+E:].T  [6144, 8192], K=2048
    gemm_hmma<128><<<dim3(G4H_/256, T_*BK_/128), 256, SMEM128>>>(
        pX3, nX3, IN_, pWih, nWih, LDIH_, IN_ + E_,
        pZpre, FNIL, FNIL, FNIL,
        pZpre, G4H_, T_*BK_, G4H_, IN_, 0, 0);

    for (int t = 0; t < T_; t++) {
        int src = t & 1;
        const float* zsrc = pZpre + (size_t)t*BK_*G4H_;
        if (t > 0) {
            gemm_hmma<128><<<dim3(G4H_/256, BK_/128), 256, SMEM128>>>(
                pH, NHH_, H_, pWhh, nWhh, H_, 0,
                zsrc, FNIL, FNIL, FNIL,
                pZ, G4H_, BK_, G4H_, H_, 0, 0);
            zsrc = pZ;
        }
        lstm_pw<<<(BK_*H_ + 255)/256, 256>>>(zsrc);
        // fc1: split-K 2, parts in d_Z, reduce applies bias+relu and emits sHd planes
        gemm_hmma<64><<<dim3(H_/256, BK_/64, 2), 256, SMEM64>>>(
            pH2, NHH_, H_, pWfc1, nWfc1, H_, 0,
            FNIL, FNIL, FNIL, FNIL,
            pZ, H_, BK_, H_, H_, 0, 1024);
        reduce_k<<<(BK_*H_ + 255)/256, 256>>>(pZ, 2, BK_*H_, H_, b_fc1, phd, 1, pHd);
        // logits: split-K 8
        gemm_hmma<64><<<dim3(2, BK_/64, 8), 256, SMEM64>>>(
            pHd, NHH_, H_, pWout, nWout, H_, 0,
            FNIL, FNIL, FNIL, FNIL,
            plogp, D_, BK_, D_, H_, 0, 256);
        reduce_k<<<(BK_*D_ + 255)/256, 256>>>(plogp, 8, BK_*D_, D_, b_out, plogits, 0, HNIL);

        softmax_kernel<<<BK_, 128>>>(pop + t*BK_, mask, gum_u + (size_t)t*BK_*D_, t, src);
        if (t > 0) topk_kernel<<<B_, 128>>>();
        beam_update<<<1, BK_>>>(t, src);
        gather_hc<<<(BK_*H_ + 255)/256, 256>>>();
        if (t > 0) {
            entfull_kernel<<<B_, 256>>>(pop + t*BK_, mask);
            wq_kernel<<<1, B_>>>(src ^ 1);
        }
    }
    epilogue<<<(11712 + 255)/256, 256>>>((float*)d_out);
}

// round 16
// speedup vs baseline: 1.9674x; 1.1625x over previous
#include <cuda_runtime.h>
#include <cuda_fp16.h>
#include <stdint.h>
#include <math.h>

#define B_ 64
#define K_ 8
#define T_ 12
#define H_ 2048
#define IN_ 2048
#define D_ 400
#define E_ 128
#define BK_ 512
#define G4H_ 8192
#define LDIH_ 4224
#define KM1_ 7
#define NHH_ ((size_t)BK_*H_)

__device__ float d_Zpre[T_*BK_*G4H_];
__device__ float d_Emb[T_*BK_*E_];
__device__ float d_ZxB[B_*G4H_];
__device__ float d_logpart[8*BK_*D_];
__device__ float d_Z[BK_*G4H_];
__device__ float d_c[BK_*H_];
__device__ float d_c2[BK_*H_];
__device__ float d_h2[BK_*H_];
__device__ float d_hd[BK_*H_];
__device__ float d_lpt[BK_*D_];
__device__ float d_gm[BK_*D_];
__device__ float d_G[2][BK_];
__device__ float d_logp[2][BK_];
__device__ float d_samp[2][BK_*T_];
__device__ float d_outs[2][BK_*T_];
__device__ float d_ent[B_];
__device__ float d_wpq[B_*KM1_];
__device__ float d_lgp[B_*KM1_];
__device__ int d_greedy[BK_];
__device__ int d_order[BK_];
__device__ int d_idxk[B_*K_];
__device__ float d_gval[B_*K_];

// fp16 h/m planes (2 stacked copies each; m = v - h, unscaled)
__device__ __half sWih[2ull*G4H_*LDIH_];
__device__ __half sWhh[2ull*G4H_*H_];
__device__ __half sWfc1[2ull*H_*H_];
__device__ __half sWout[2ull*D_*H_];
__device__ __half sX3[2ull*T_*BK_*IN_];
__device__ __half sEmb[2ull*T_*BK_*E_];
__device__ __half sXf[2ull*B_*IN_];
__device__ __half sH[2ull*BK_*H_];
__device__ __half sH2[2ull*BK_*H_];
__device__ __half sHd[2ull*BK_*H_];

__device__ __forceinline__ float sigf(float x) { return 1.f / (1.f + expf(-x)); }
__device__ __forceinline__ unsigned orderf(float f) {
    unsigned u = __float_as_uint(f);
    return (u & 0x80000000u) ? ~u : (u | 0x80000000u);
}
__device__ __forceinline__ float unorderf(unsigned e) {
    unsigned b = (e & 0x80000000u) ? (e ^ 0x80000000u) : ~e;
    return __uint_as_float(b);
}
__device__ __forceinline__ uint32_t smem_u32(const void* p) {
    uint32_t a;
    asm("{ .reg .u64 t; cvta.to.shared.u64 t, %1; cvt.u32.u64 %0, t; }" : "=r"(a) : "l"(p));
    return a;
}
__device__ __forceinline__ void ldm4(uint32_t* r, uint32_t addr) {
    asm volatile("ldmatrix.sync.aligned.m8n8.x4.shared.b16 {%0,%1,%2,%3}, [%4];"
        : "=r"(r[0]), "=r"(r[1]), "=r"(r[2]), "=r"(r[3]) : "r"(addr));
}
__device__ __forceinline__ void mma16816(float* c, const uint32_t* a, const uint32_t* b) {
    asm volatile("mma.sync.aligned.m16n8k16.row.col.f32.f16.f16.f32 "
        "{%0,%1,%2,%3}, {%4,%5,%6,%7}, {%8,%9}, {%0,%1,%2,%3};"
        : "+f"(c[0]), "+f"(c[1]), "+f"(c[2]), "+f"(c[3])
        : "r"(a[0]), "r"(a[1]), "r"(a[2]), "r"(a[3]), "r"(b[0]), "r"(b[1]));
}
__device__ __forceinline__ void cpa16(uint32_t dst, const void* src, int sz) {
    asm volatile("cp.async.ca.shared.global [%0], [%1], 16, %2;" :: "r"(dst), "l"(src), "r"(sz) : "memory");
}
__device__ __forceinline__ void wsplit2(__half* base, size_t plane, size_t i, float v) {
    __half h = __float2half(v);
    base[i] = h;
    base[plane + i] = __float2half(v - __half2float(h));
}

// =====================================================================
// Fused fp16 split HMMA GEMM: per chunk stages A_h,A_m,B_h,B_m and
// accumulates hh + hm + mh in one fp32 accumulator (m unscaled).
// Tile BM x 256, BK=64, 256 threads (8 warps, warp tile (BM/2) x 64).
// cp.async double-buffered. kchunk != 0: split-K over gridDim.z.
// =====================================================================
template<int BM>
__global__ __launch_bounds__(256)
void gemm_hmma(const __half* A, size_t Asz, int lda,
               const __half* Bm, size_t Bsz, int ldb, int kbB,
               const float* Cin, const float* bias, const float* bias2, const float* zxb,
               float* C, int ldc, int M, int N, int K, int do_relu, int kchunk)
{
    extern __shared__ char smem[];
    constexpr int MI = BM / 32;
    constexpr int APB = BM * 128;          // bytes per A plane tile
    constexpr int BPB = 32768;             // bytes per B plane tile (256 x 128B)
    constexpr int CHB = 2*APB + 2*BPB;     // chunk bytes

    if (kchunk) {
        int kz = blockIdx.z;
        A += (size_t)kz * kchunk;
        kbB += kz * kchunk;
        C += (size_t)kz * M * ldc;
        K = kchunk;
    }
    const int tid = threadIdx.x;
    const int wid = tid >> 5;
    const int lane = tid & 31;
    const int bm = blockIdx.y * BM;
    const int bn = blockIdx.x * 256;
    const int wm = (wid & 1) * (BM / 2);
    const int wn = (wid >> 1) * 64;
    const uint32_t sbase = smem_u32(smem);

    float acc[MI][8][4];
#pragma unroll
    for (int i = 0; i < MI; i++)
#pragma unroll
        for (int j = 0; j < 8; j++)
#pragma unroll
            for (int e = 0; e < 4; e++) acc[i][j][e] = 0.f;

    const int NC = K >> 6;

    auto stage_async = [&](int kc, int buf) {
        int ka = kc * 64;
        int kb = kbB + kc * 64;
        uint32_t base = sbase + buf * CHB;
#pragma unroll
        for (int pl = 0; pl < 2; pl++) {
            const __half* Ap = A + (size_t)pl * Asz;
            uint32_t Ad = base + pl * APB;
#pragma unroll
            for (int i = 0; i < BM/32; i++) {
                int idx = tid + i * 256;
                int r = idx >> 3;
                int cb = (idx & 7) << 4;
                int ok = (bm + r < M);
                const char* g = ok ? (const char*)(Ap + (size_t)(bm + r) * lda + ka) + cb
                                   : (const char*)Ap;
                cpa16(Ad + r * 128 + (cb ^ ((r & 7) * 16)), g, ok ? 16 : 0);
            }
        }
#pragma unroll
        for (int pl = 0; pl < 2; pl++) {
            const __half* Bp = Bm + (size_t)pl * Bsz;
            uint32_t Bd = base + 2*APB + pl * BPB;
#pragma unroll
            for (int i = 0; i < 8; i++) {
                int idx = tid + i * 256;
                int r = idx >> 3;
                int cb = (idx & 7) << 4;
                int ok = (bn + r < N);
                const char* g = ok ? (const char*)(Bp + (size_t)(bn + r) * ldb + kb) + cb
                                   : (const char*)Bp;
                cpa16(Bd + r * 128 + (cb ^ ((r & 7) * 16)), g, ok ? 16 : 0);
            }
        }
        asm volatile("cp.async.commit_group;" ::: "memory");
    };

    auto compute = [&](int buf) {
        uint32_t base = sbase + buf * CHB;
#pragma unroll
        for (int kk = 0; kk < 4; kk++) {
            uint32_t afh[MI][4], afm[MI][4];
            {
                int ro = ((lane >> 3) & 1) * 8 + (lane & 7);
                int co = kk * 32 + ((lane >> 4) & 1) * 16;
#pragma unroll
                for (int i = 0; i < MI; i++) {
                    int r = wm + i * 16 + ro;
                    uint32_t off = r * 128 + (co ^ ((r & 7) * 16));
                    ldm4(afh[i], base + off);
                    ldm4(afm[i], base + APB + off);
                }
            }
            uint32_t bfh[8][2], bfm[8][2];
            {
                int ro = ((lane >> 4) & 1) * 8 + (lane & 7);
                int co = kk * 32 + ((lane >> 3) & 1) * 16;
#pragma unroll
                for (int j2 = 0; j2 < 4; j2++) {
                    int r = wn + j2 * 16 + ro;
                    uint32_t off = r * 128 + (co ^ ((r & 7) * 16));
                    uint32_t t4[4];
                    ldm4(t4, base + 2*APB + off);
                    bfh[j2*2][0] = t4[0]; bfh[j2*2][1] = t4[1];
                    bfh[j2*2+1][0] = t4[2]; bfh[j2*2+1][1] = t4[3];
                    ldm4(t4, base + 2*APB + BPB + off);
                    bfm[j2*2][0] = t4[0]; bfm[j2*2][1] = t4[1];
                    bfm[j2*2+1][0] = t4[2]; bfm[j2*2+1][1] = t4[3];
                }
            }
#pragma unroll
            for (int i = 0; i < MI; i++)
#pragma unroll
                for (int j = 0; j < 8; j++) {
                    mma16816(acc[i][j], afh[i], bfh[j]);
                    mma16816(acc[i][j], afh[i], bfm[j]);
                    mma16816(acc[i][j], afm[i], bfh[j]);
                }
        }
    };

    stage_async(0, 0);
    asm volatile("cp.async.wait_group 0;" ::: "memory");
    __syncthreads();
    for (int c = 0; c < NC; c++) {
        if (c + 1 < NC) stage_async(c + 1, (c + 1) & 1);
        compute(c & 1);
        if (c + 1 < NC) asm volatile("cp.async.wait_group 0;" ::: "memory");
        __syncthreads();
    }

#pragma unroll
    for (int i = 0; i < MI; i++) {
#pragma unroll
        for (int j = 0; j < 8; j++) {
            int r0 = bm + wm + i * 16 + (lane >> 2);
            int c0 = bn + wn + j * 8 + (lane & 3) * 2;
#pragma unroll
            for (int e = 0; e < 4; e++) {
                int m = r0 + (e >> 1) * 8;
                int n = c0 + (e & 1);
                if (m >= M || n >= N) continue;
                float v = acc[i][j][e];
                if (Cin) v += Cin[(size_t)m * ldc + n];
                if (bias) v += bias[n];
                if (bias2) v += bias2[n];
                if (zxb) v += zxb[(size_t)(m & 63) * ldc + n];
                if (do_relu) v = fmaxf(v, 0.f);
                C[(size_t)m * ldc + n] = v;
            }
        }
    }
}

// fp32 -> fp16 h/m planes
__global__ void split2(const float* in, __half* out, size_t n) {
    size_t i = (size_t)blockIdx.x * blockDim.x + threadIdx.x;
    if (i >= n) return;
    wsplit2(out, n, i, in[i]);
}

// split-K reduce; optional fp16 plane output (plane size = total)
__global__ void reduce_k(const float* parts, int nparts, int total, int ncols,
                         const float* bias, float* out, int do_relu, __half* bout) {
    int i = blockIdx.x * blockDim.x + threadIdx.x;
    if (i >= total) return;
    float s = 0.f;
    for (int p = 0; p < nparts; p++) s += parts[(size_t)p * total + i];
    if (bias) s += bias[i % ncols];
    if (do_relu) s = fmaxf(s, 0.f);
    out[i] = s;
    if (bout) wsplit2(bout, (size_t)total, (size_t)i, s);
}

__global__ void zero_init() {
    int i = blockIdx.x * blockDim.x + threadIdx.x;
    int stride = gridDim.x * blockDim.x;
    for (int j = i; j < BK_*H_; j += stride) d_c[j] = 0.f;
    if (i < BK_) { d_G[0][i] = 0.f; d_logp[0][i] = 0.f; }
    if (i < BK_*T_) { d_samp[0][i] = 0.f; d_outs[0][i] = 0.f; }
    if (i < B_) d_ent[i] = 0.f;
}

__global__ void emb_kernel(const int* pop_all, const float* W_emb, const float* b_emb) {
    int i = blockIdx.x * blockDim.x + threadIdx.x;
    if (i >= T_*BK_*E_) return;
    int row = i >> 7;
    int e = i & 127;
    int p = pop_all[row];
    d_Emb[i] = fmaxf(W_emb[e*D_ + p] + b_emb[e], 0.f);
}

// LSTM pointwise; writes h2 fp32 + sH2 planes
__global__ void lstm_pw(const float* zsrc) {
    int i = blockIdx.x * blockDim.x + threadIdx.x;
    if (i >= BK_*H_) return;
    int bk = i >> 11;
    int col = i & 2047;
    const float* zr = zsrc + (size_t)bk * G4H_;
    float cn = sigf(zr[H_ + col]) * d_c[i] + sigf(zr[col]) * tanhf(zr[2*H_ + col]);
    d_c2[i] = cn;
    float hv = sigf(zr[3*H_ + col]) * tanhf(cn);
    d_h2[i] = hv;
    wsplit2(sH2, NHH_, (size_t)i, hv);
}

// fused: logits split-K reduce + masked log_softmax + greedy + (t>0) gumbel g
__global__ void softmax_kernel(const int* pop_t, const float* mask, const float* u_t,
                               const float* b_out, int t, int src) {
    int bk = blockIdx.x;
    int tid = threadIdx.x;
    __shared__ float sm[D_];
    __shared__ float red[128];
    __shared__ unsigned long long redu[128];
    const float* mrow = mask + (size_t)pop_t[bk] * D_;
    float NEG_INF = __int_as_float(0xff800000);
    float lmax = NEG_INF;
    for (int d = tid; d < D_; d += 128) {
        float s = 0.f;
#pragma unroll
        for (int p = 0; p < 8; p++) s += d_logpart[(size_t)p * BK_ * D_ + bk * D_ + d];
        float v = s + b_out[d] + mrow[d];
        sm[d] = v;
        lmax = fmaxf(lmax, v);
    }
    red[tid] = lmax; __syncthreads();
    for (int s = 64; s > 0; s >>= 1) { if (tid < s) red[tid] = fmaxf(red[tid], red[tid+s]); __syncthreads(); }
    float M = red[0]; __syncthreads();
    float ssum = 0.f;
    for (int d = tid; d < D_; d += 128) ssum += expf(sm[d] - M);
    red[tid] = ssum; __syncthreads();
    for (int s = 64; s > 0; s >>= 1) { if (tid < s) red[tid] += red[tid+s]; __syncthreads(); }
    float logZ = M + logf(red[0]);
    unsigned long long bkey = 0ull;
    for (int d = tid; d < D_; d += 128) {
        unsigned long long key = ((unsigned long long)orderf(sm[d]) << 32) | (unsigned)(0xFFFFFFFFu - d);
        bkey = bkey > key ? bkey : key;
    }
    redu[tid] = bkey; __syncthreads();
    for (int s = 64; s > 0; s >>= 1) { if (tid < s) redu[tid] = redu[tid] > redu[tid+s] ? redu[tid] : redu[tid+s]; __syncthreads(); }
    if (tid == 0) d_greedy[bk] = (int)(0xFFFFFFFFu - (unsigned)(redu[0] & 0xFFFFFFFFu));
    for (int d = tid; d < D_; d += 128) d_lpt[bk*D_ + d] = sm[d] - logZ;
    if (t > 0) {
        float lpc = d_logp[src][bk];
        float Gc = d_G[src][bk];
        __syncthreads();
        for (int d = tid; d < D_; d += 128) {
            float uu = fminf(fmaxf(u_t[bk*D_ + d], 1e-9f), 1.f - 1e-9f);
            sm[d] = (sm[d] - logZ) + lpc + (-logf(-logf(uu)));
        }
        __syncthreads();
        float m2 = NEG_INF;
        for (int d = tid; d < D_; d += 128) m2 = fmaxf(m2, sm[d]);
        red[tid] = m2; __syncthreads();
        for (int s = 64; s > 0; s >>= 1) { if (tid < s) red[tid] = fmaxf(red[tid], red[tid+s]); __syncthreads(); }
        float Zm = red[0];
        for (int d = tid; d < D_; d += 128) {
            float gp = sm[d];
            float v = Gc - gp + log1pf(-expf(gp - Zm));
            d_gm[bk*D_ + d] = Gc - fmaxf(v, 0.f) - log1pf(expf(-fabsf(v)));
        }
    }
}

__global__ void topk_kernel() {
    int b = blockIdx.x;
    int tid = threadIdx.x;
    __shared__ unsigned long long red[128];
    __shared__ unsigned long long picked[K_];
    for (int it = 0; it < K_; it++) {
        unsigned long long best = 0ull;
        for (int cidx = tid; cidx < K_*D_; cidx += 128) {
            int k = cidx / D_;
            int d = cidx - k*D_;
            float v = d_gm[(k*B_ + b)*D_ + d];
            unsigned long long key = ((unsigned long long)orderf(v) << 32) | (unsigned)(0xFFFFFFFFu - cidx);
            bool skip = false;
            for (int j = 0; j < it; j++) { if (picked[j] == key) skip = true; }
            if (!skip) best = best > key ? best : key;
        }
        red[tid] = best; __syncthreads();
        for (int s = 64; s > 0; s >>= 1) { if (tid < s) red[tid] = red[tid] > red[tid+s] ? red[tid] : red[tid+s]; __syncthreads(); }
        if (tid == 0) {
            unsigned long long w = red[0];
            picked[it] = w;
            d_idxk[b*K_ + it] = (int)(0xFFFFFFFFu - (unsigned)(w & 0xFFFFFFFFu));
            d_gval[b*K_ + it] = unorderf((unsigned)(w >> 32));
        }
        __syncthreads();
    }
}

__global__ void beam_update(int t, int src) {
    int bk = threadIdx.x;
    int dst = src ^ 1;
    int k = bk >> 6;
    int b = bk & 63;
    int order;
    int sample;
    float Gn;
    if (t == 0) { order = bk; sample = d_greedy[bk]; Gn = d_G[src][bk]; }
    else {
        int cidx = d_idxk[b*K_ + k];
        int ks = cidx / D_;
        sample = cidx - ks*D_;
        order = ks*B_ + b;
        Gn = d_gval[b*K_ + k];
    }
    float sel = d_lpt[order*D_ + sample];
    d_G[dst][bk] = Gn;
    d_logp[dst][bk] = d_logp[src][order] + ((t == 0) ? 0.f : sel);
    d_order[bk] = order;
    for (int tt = 0; tt < T_; tt++) {
        d_samp[dst][bk*T_ + tt] = d_samp[src][order*T_ + tt];
        d_outs[dst][bk*T_ + tt] = d_outs[src][order*T_ + tt];
    }
    d_samp[dst][bk*T_ + t] = (float)sample;
    d_outs[dst][bk*T_ + t] = sel;
}

// gather h/c by beam order; writes c fp32 + sH planes
__global__ void gather_hc() {
    int i = blockIdx.x * blockDim.x + threadIdx.x;
    if (i >= BK_*H_) return;
    int bk = i >> 11;
    int col = i & 2047;
    int o = d_order[bk];
    float hv = d_h2[o*H_ + col];
    d_c[i] = d_c2[o*H_ + col];
    wsplit2(sH, NHH_, (size_t)i, hv);
}

// fused entropy + importance weights: one block per image b (256 thr, warps 0..6 active)
__global__ void entwq_kernel(const int* pop_t, const float* mask, int dst) {
    int b = blockIdx.x;
    int warp = threadIdx.x >> 5;
    int lane = threadIdx.x & 31;
    __shared__ float ent_s[KM1_];
    if (warp < KM1_) {
        int o = d_order[warp*B_ + b];
        const float* lpr = d_lpt + o*D_;
        const float* mrow = mask + (size_t)pop_t[o] * D_;
        float s = 0.f;
        for (int d = lane; d < D_; d += 32) {
            float lp = lpr[d];
            if (mrow[d] == 0.f) s += lp * expf(lp);
        }
        for (int off = 16; off; off >>= 1) s += __shfl_down_sync(0xffffffffu, s, off);
        if (lane == 0) ent_s[warp] = s;
    }
    __syncthreads();
    if (threadIdx.x == 0) {
        float gk = d_gval[b*K_ + (K_-1)];
        float wsum = 0.f;
        float upd = 0.f;
        for (int k = 0; k < KM1_; k++) {
            float phi = d_logp[dst][k*B_ + b];
            float x = gk - phi;
            float gls;
            if (x >= 10.f) { float y = expf(-x); gls = -x - 0.5f*y + y*y*(1.f/24.f); }
            else gls = logf(-expm1f(-expf(-x)));
            float w = expf(phi - gls);
            d_wpq[b*KM1_ + k] = w;
            d_lgp[b*KM1_ + k] = phi;
            wsum += w;
            upd += w * ent_s[k];
        }
        d_ent[b] += upd / wsum;
    }
}

__global__ void epilogue(float* out) {
    int i = blockIdx.x * blockDim.x + threadIdx.x;
    if (i >= 11712) return;
    if (i < 5376) {
        int b = i / 84;
        int r = i % 84;
        out[i] = d_outs[0][((r / T_)*B_ + b)*T_ + (r % T_)];
    } else if (i < 10752) {
        int q = i - 5376;
        int b = q / 84;
        int r = q % 84;
        out[i] = d_samp[0][((r / T_)*B_ + b)*T_ + (r % T_)];
    } else if (i < 10816) out[i] = d_ent[i - 10752];
    else if (i < 11264) out[i] = d_wpq[i - 10816];
    else out[i] = d_lgp[i - 11264];
}

#define SMEM128 196608
#define SMEM64 163840
#define FNIL (const float*)0
#define HNIL (__half*)0

extern "C" void kernel_launch(void* const* d_in, const int* in_sizes, int n_in,
                              void* d_out, int out_size)
{
    const float* x_f = (const float*)d_in[0];
    const float* x_f3 = (const float*)d_in[1];
    const float* gum_u = (const float*)d_in[2];
    const int* pop = (const int*)d_in[3];
    const float* mask = (const float*)d_in[4];
    const float* W_emb = (const float*)d_in[5];
    const float* b_emb = (const float*)d_in[6];
    const float* W_ih = (const float*)d_in[7];
    const float* W_hh = (const float*)d_in[8];
    const float* b_ih = (const float*)d_in[9];
    const float* b_hh = (const float*)d_in[10];
    const float* W_fc1 = (const float*)d_in[11];
    const float* b_fc1 = (const float*)d_in[12];
    const float* W_out = (const float*)d_in[13];
    const float* b_out = (const float*)d_in[14];

    float* pZpre;
    float* pEmb;
    float* pZxB;
    float* pZ;
    float* phd;
    float* plogp;
    cudaGetSymbolAddress((void**)&pZpre, d_Zpre);
    cudaGetSymbolAddress((void**)&pEmb, d_Emb);
    cudaGetSymbolAddress((void**)&pZxB, d_ZxB);
    cudaGetSymbolAddress((void**)&pZ, d_Z);
    cudaGetSymbolAddress((void**)&phd, d_hd);
    cudaGetSymbolAddress((void**)&plogp, d_logpart);
    __half* pWih;
    __half* pWhh;
    __half* pWfc1;
    __half* pWout;
    __half* pX3;
    __half* pSEmb;
    __half* pXf;
    __half* pH;
    __half* pH2;
    __half* pHd;
    cudaGetSymbolAddress((void**)&pWih, sWih);
    cudaGetSymbolAddress((void**)&pWhh, sWhh);
    cudaGetSymbolAddress((void**)&pWfc1, sWfc1);
    cudaGetSymbolAddress((void**)&pWout, sWout);
    cudaGetSymbolAddress((void**)&pX3, sX3);
    cudaGetSymbolAddress((void**)&pSEmb, sEmb);
    cudaGetSymbolAddress((void**)&pXf, sXf);
    cudaGetSymbolAddress((void**)&pH, sH);
    cudaGetSymbolAddress((void**)&pH2, sH2);
    cudaGetSymbolAddress((void**)&pHd, sHd);

    cudaFuncSetAttribute(gemm_hmma<128>, cudaFuncAttributeMaxDynamicSharedMemorySize, SMEM128);
    cudaFuncSetAttribute(gemm_hmma<64>, cudaFuncAttributeMaxDynamicSharedMemorySize, SMEM64);

    zero_init<<<2048, 512>>>();
    emb_kernel<<<(T_*BK_*E_ + 255)/256, 256>>>(pop, W_emb, b_emb);

    size_t nWih = (size_t)G4H_*LDIH_;
    size_t nWhh = (size_t)G4H_*H_;
    size_t nWfc1 = (size_t)H_*H_;
    size_t nWout = (size_t)D_*H_;
    size_t nX3 = (size_t)T_*BK_*IN_;
    size_t nEmb = (size_t)T_*BK_*E_;
    size_t nXf = (size_t)B_*IN_;
    split2<<<(unsigned)((nWih + 255)/256), 256>>>(W_ih, pWih, nWih);
    split2<<<(unsigned)((nWhh + 255)/256), 256>>>(W_hh, pWhh, nWhh);
    split2<<<(unsigned)((nWfc1 + 255)/256), 256>>>(W_fc1, pWfc1, nWfc1);
    split2<<<(unsigned)((nWout + 255)/256), 256>>>(W_out, pWout, nWout);
    split2<<<(unsigned)((nX3 + 255)/256), 256>>>(x_f3, pX3, nX3);
    split2<<<(unsigned)((nEmb + 255)/256), 256>>>(pEmb, pSEmb, nEmb);
    split2<<<(unsigned)((nXf + 255)/256), 256>>>(x_f, pXf, nXf);

    // ZxB = x_f @ W_ih[:, :IN].T  [64, 8192], split-K 4 (parts in d_Z)
    gemm_hmma<64><<<dim3(G4H_/256, 1, 4), 256, SMEM64>>>(
        pXf, nXf, IN_, pWih, nWih, LDIH_, 0,
        FNIL, FNIL, FNIL, FNIL,
        pZ, G4H_, B_, G4H_, IN_, 0, 512);
    reduce_k<<<(B_*G4H_ + 255)/256, 256>>>(pZ, 4, B_*G4H_, G4H_, FNIL, pZxB, 0, HNIL);

    // Zpre = Emb @ W_ih[:, IN:IN+E].T + b_ih + b_hh + ZxB[b]  [6144, 8192], K=128
    gemm_hmma<128><<<dim3(G4H_/256, T_*BK_/128), 256, SMEM128>>>(
        pSEmb, nEmb, E_, pWih, nWih, LDIH_, IN_,
        FNIL, b_ih, b_hh, pZxB,
        pZpre, G4H_, T_*BK_, G4H_, E_, 0, 0);

    // Zpre += x_f3 @ W_ih[:, IN+E:].T  [6144, 8192], K=2048
    gemm_hmma<128><<<dim3(G4H_/256, T_*BK_/128), 256, SMEM128>>>(
        pX3, nX3, IN_, pWih, nWih, LDIH_, IN_ + E_,
        pZpre, FNIL, FNIL, FNIL,
        pZpre, G4H_, T_*BK_, G4H_, IN_, 0, 0);

    for (int t = 0; t < T_; t++) {
        int src = t & 1;
        const float* zsrc = pZpre + (size_t)t*BK_*G4H_;
        if (t > 0) {
            gemm_hmma<128><<<dim3(G4H_/256, BK_/128), 256, SMEM128>>>(
                pH, NHH_, H_, pWhh, nWhh, H_, 0,
                zsrc, FNIL, FNIL, FNIL,
                pZ, G4H_, BK_, G4H_, H_, 0, 0);
            zsrc = pZ;
        }
        lstm_pw<<<(BK_*H_ + 255)/256, 256>>>(zsrc);
        // fc1: split-K 2, parts in d_Z, reduce applies bias+relu and emits sHd planes
        gemm_hmma<64><<<dim3(H_/256, BK_/64, 2), 256, SMEM64>>>(
            pH2, NHH_, H_, pWfc1, nWfc1, H_, 0,
            FNIL, FNIL, FNIL, FNIL,
            pZ, H_, BK_, H_, H_, 0, 1024);
        reduce_k<<<(BK_*H_ + 255)/256, 256>>>(pZ, 2, BK_*H_, H_, b_fc1, phd, 1, pHd);
        // logits: split-K 8 (reduce fused into softmax)
        gemm_hmma<64><<<dim3(2, BK_/64, 8), 256, SMEM64>>>(
            pHd, NHH_, H_, pWout, nWout, H_, 0,
            FNIL, FNIL, FNIL, FNIL,
            plogp, D_, BK_, D_, H_, 0, 256);

        softmax_kernel<<<BK_, 128>>>(pop + t*BK_, mask, gum_u + (size_t)t*BK_*D_, b_out, t, src);
        if (t > 0) topk_kernel<<<B_, 128>>>();
        beam_update<<<1, BK_>>>(t, src);
        gather_hc<<<(BK_*H_ + 255)/256, 256>>>();
        if (t > 0) entwq_kernel<<<B_, 256>>>(pop + t*BK_, mask, src ^ 1);
    }
    epilogue<<<(11712 + 255)/256, 256>>>((float*)d_out);
}